// round 2
// baseline (speedup 1.0000x reference)
#include <cuda_runtime.h>
#include <math.h>

#define TPB 256
#define NJP 64   // 64 packed j-pairs = 128 hidden units

typedef unsigned long long u64;

__device__ __forceinline__ u64 pk2(float x, float y) {
    u64 r; asm("mov.b64 %0, {%1,%2};" : "=l"(r) : "f"(x), "f"(y)); return r;
}
__device__ __forceinline__ void upk2(u64 v, float& x, float& y) {
    asm("mov.b64 {%0,%1}, %2;" : "=f"(x), "=f"(y) : "l"(v));
}
__device__ __forceinline__ u64 ffma2(u64 a, u64 b, u64 c) {
    u64 d; asm("fma.rn.f32x2 %0, %1, %2, %3;" : "=l"(d) : "l"(a), "l"(b), "l"(c)); return d;
}
__device__ __forceinline__ float gelu_f(float x) {
    // exact (non-approximate) GELU: x * 0.5 * (1 + erf(x/sqrt(2)))
    return 0.5f * x * (1.0f + erff(x * 0.70710678118654752440f));
}

// Forward kinematics for the 7-DOF Panda chain -> 7 keypoint positions.
// Fixed joint transforms are axis-aligned rotations; full unroll lets ptxas fold zeros.
__device__ __forceinline__ void fk_eval(const float th[7], float kp[21]) {
    const float FR[7][9] = {
        {1,0,0,  0,1,0,   0,0,1},   // rx = 0
        {1,0,0,  0,0,1,   0,-1,0},  // rx = -pi/2
        {1,0,0,  0,0,-1,  0,1,0},   // rx = +pi/2
        {1,0,0,  0,0,-1,  0,1,0},
        {1,0,0,  0,0,1,   0,-1,0},
        {1,0,0,  0,0,-1,  0,1,0},
        {1,0,0,  0,0,-1,  0,1,0}
    };
    const float FT[7][3] = {
        {0.f,0.f,0.333f},{0.f,0.f,0.f},{0.f,-0.316f,0.f},{0.0825f,0.f,0.f},
        {-0.0825f,0.384f,0.f},{0.f,0.f,0.f},{0.088f,0.f,0.f}
    };
    float r[9] = {1,0,0, 0,1,0, 0,0,1};
    float t[3] = {0,0,0};
    kp[0] = 0.f; kp[1] = 0.f; kp[2] = 0.f;
    int w = 3;
    #pragma unroll
    for (int i = 0; i < 7; i++) {
        float s, c; sincosf(th[i], &s, &c);
        // step.R = FR[i] @ Rz(theta)
        float sr[9];
        sr[0] =  FR[i][0]*c + FR[i][1]*s;  sr[1] = -FR[i][0]*s + FR[i][1]*c;  sr[2] = FR[i][2];
        sr[3] =  FR[i][3]*c + FR[i][4]*s;  sr[4] = -FR[i][3]*s + FR[i][4]*c;  sr[5] = FR[i][5];
        sr[6] =  FR[i][6]*c + FR[i][7]*s;  sr[7] = -FR[i][6]*s + FR[i][7]*c;  sr[8] = FR[i][8];
        // t' = r @ FT[i] + t
        float nt0 = r[0]*FT[i][0] + r[1]*FT[i][1] + r[2]*FT[i][2] + t[0];
        float nt1 = r[3]*FT[i][0] + r[4]*FT[i][1] + r[5]*FT[i][2] + t[1];
        float nt2 = r[6]*FT[i][0] + r[7]*FT[i][1] + r[8]*FT[i][2] + t[2];
        // r' = r @ sr
        float nr[9];
        #pragma unroll
        for (int a = 0; a < 3; a++)
            #pragma unroll
            for (int bq = 0; bq < 3; bq++)
                nr[a*3+bq] = r[a*3+0]*sr[bq] + r[a*3+1]*sr[3+bq] + r[a*3+2]*sr[6+bq];
        #pragma unroll
        for (int q = 0; q < 9; q++) r[q] = nr[q];
        t[0] = nt0; t[1] = nt1; t[2] = nt2;
        if (i == 1 || i == 2 || i == 3 || i == 5 || i == 6) {
            kp[w] = t[0]; kp[w+1] = t[1]; kp[w+2] = t[2]; w += 3;
        }
    }
    // kp[6] = joint8 translation = t + r @ (0,0,0.107); hand rot-z doesn't move translation
    kp[18] = t[0] + r[2]*0.107f;
    kp[19] = t[1] + r[5]*0.107f;
    kp[20] = t[2] + r[8]*0.107f;
}

// Shared memory layout (float offsets)
#define OFF_W1   0        // 28*128 = 3584
#define OFF_W2   3584     // 128*128 = 16384
#define OFF_W3   19968    // 128*8 (padded) = 1024
#define OFF_B1   20992
#define OFF_G1   21120
#define OFF_BE1  21248
#define OFF_B2   21376
#define OFF_G2   21504
#define OFF_BE2  21632
#define OFF_B3   21760    // 8 (padded)
#define OFF_H    21768    // 128*TPB
#define SMEM_FLOATS (OFF_H + 128*TPB)

__global__ void __launch_bounds__(TPB, 1)
irm_kernel(const float* __restrict__ ang, const float* __restrict__ tgt,
           const float* __restrict__ Kc,  const float* __restrict__ Re,
           const float* __restrict__ te,  const int* __restrict__ vmk,
           const float* __restrict__ W1,  const float* __restrict__ b1,
           const float* __restrict__ g1,  const float* __restrict__ be1,
           const float* __restrict__ W2,  const float* __restrict__ b2,
           const float* __restrict__ g2,  const float* __restrict__ be2,
           const float* __restrict__ W3,  const float* __restrict__ b3,
           const float* __restrict__ slog, float* __restrict__ out, int Bn)
{
    extern __shared__ float sm[];
    float* sW1  = sm + OFF_W1;
    float* sW2  = sm + OFF_W2;
    float* sW3  = sm + OFF_W3;
    float* sb1  = sm + OFF_B1;
    float* sg1  = sm + OFF_G1;
    float* sbe1 = sm + OFF_BE1;
    float* sb2  = sm + OFF_B2;
    float* sg2  = sm + OFF_G2;
    float* sbe2 = sm + OFF_BE2;
    float* sb3  = sm + OFF_B3;
    float* sH   = sm + OFF_H;

    const int tid = threadIdx.x;
    for (int i = tid; i < 3584;  i += TPB) sW1[i] = W1[i];
    for (int i = tid; i < 16384; i += TPB) sW2[i] = W2[i];
    for (int i = tid; i < 1024;  i += TPB) {
        int k = i >> 3, j = i & 7;
        sW3[i] = (j < 7) ? W3[k*7 + j] : 0.f;
    }
    if (tid < 128) {
        sb1[tid]  = b1[tid];  sg1[tid] = g1[tid];  sbe1[tid] = be1[tid];
        sb2[tid]  = b2[tid];  sg2[tid] = g2[tid];  sbe2[tid] = be2[tid];
    }
    if (tid < 8) sb3[tid] = (tid < 7) ? b3[tid] : 0.f;
    __syncthreads();

    const int b = blockIdx.x * TPB + tid;
    if (b >= Bn) return;

    // per-element inputs
    float th[7];
    #pragma unroll
    for (int j = 0; j < 7; j++) th[j] = ang[(size_t)b*7 + j];
    float Rm[9], Km[9], tv[3], tg[14];
    #pragma unroll
    for (int j = 0; j < 9; j++) { Rm[j] = Re[(size_t)b*9 + j]; Km[j] = Kc[(size_t)b*9 + j]; }
    #pragma unroll
    for (int j = 0; j < 3; j++) tv[j] = te[(size_t)b*3 + j];
    #pragma unroll
    for (int j = 0; j < 14; j++) tg[j] = tgt[(size_t)b*14 + j];
    const float vm = (vmk[b] != 0) ? 1.f : 0.f;   // bool materialized as int32

    const float LO[7] = {-2.8973f,-1.7628f,-2.8973f,-3.0718f,-2.8973f,-0.0175f,-2.8973f};
    const float HI[7] = { 2.8973f, 1.7628f, 2.8973f,-0.0698f, 2.8973f, 3.7525f, 2.8973f};

    float kp[21];
    fk_eval(th, kp);

    float* outA = out + (size_t)28 * Bn;   // all_angles (4,B,7)
    float* outK = out + (size_t)56 * Bn;   // all_kp     (4,B,7,3)

    #pragma unroll
    for (int j = 0; j < 7; j++)  outA[(size_t)b*7 + j]  = th[j];
    #pragma unroll
    for (int j = 0; j < 21; j++) outK[(size_t)b*21 + j] = kp[j];

    for (int it = 0; it < 3; it++) {
        // ---- features: project keypoints, residuals, magnitudes ----
        float x[28];
        #pragma unroll
        for (int k = 0; k < 7; k++) {
            float px = kp[3*k], py = kp[3*k+1], pz = kp[3*k+2];
            float cx = Rm[0]*px + Rm[1]*py + Rm[2]*pz + tv[0];
            float cy = Rm[3]*px + Rm[4]*py + Rm[5]*pz + tv[1];
            float cz = Rm[6]*px + Rm[7]*py + Rm[8]*pz + tv[2];
            float z  = fmaxf(cz, 1e-6f);
            float inv = 1.0f / z;
            float nx = cx*inv, ny = cy*inv, nz = cz*inv;
            float u = Km[0]*nx + Km[1]*ny + Km[2]*nz;
            float v = Km[3]*nx + Km[4]*ny + Km[5]*nz;
            float dx = (tg[2*k]   - u) * vm;
            float dy = (tg[2*k+1] - v) * vm;
            x[2*k] = dx; x[2*k+1] = dy;
            x[21+k] = sqrtf(dx*dx + dy*dy);
        }
        #pragma unroll
        for (int j = 0; j < 7; j++) x[14+j] = th[j];

        // ---- GEMM1: (28)->(128), packed f32x2 accumulators ----
        u64 acc[NJP];
        {
            const u64* pb1 = (const u64*)sb1;
            #pragma unroll
            for (int jp = 0; jp < NJP; jp++) acc[jp] = pb1[jp];
            const ulonglong2* W1q = (const ulonglong2*)sW1;
            #pragma unroll 4
            for (int k = 0; k < 28; k++) {
                u64 xx = pk2(x[k], x[k]);
                #pragma unroll
                for (int jq = 0; jq < 32; jq++) {
                    ulonglong2 w = W1q[k*32 + jq];
                    acc[2*jq]   = ffma2(xx, w.x, acc[2*jq]);
                    acc[2*jq+1] = ffma2(xx, w.y, acc[2*jq+1]);
                }
            }
        }
        // stash raw pre-activation to sH (per-thread column, conflict-free)
        #pragma unroll
        for (int jp = 0; jp < NJP; jp++) {
            float a0, a1; upk2(acc[jp], a0, a1);
            sH[(2*jp)*TPB + tid]   = a0;
            sH[(2*jp+1)*TPB + tid] = a1;
        }
        // GELU in a rolled loop (keeps erf poly out of the unrolled body), gather stats
        float sum = 0.f, sq = 0.f;
        #pragma unroll 4
        for (int k = 0; k < 128; k++) {
            float a = gelu_f(sH[k*TPB + tid]);
            sH[k*TPB + tid] = a;
            sum += a; sq += a*a;
        }
        float mu   = sum * (1.f/128.f);
        float var  = sq  * (1.f/128.f) - mu*mu;
        float rstd = rsqrtf(var + 1e-5f);

        // ---- GEMM2: (128)->(128); LN applied lazily at read ----
        {
            const u64* pb2 = (const u64*)sb2;
            #pragma unroll
            for (int jp = 0; jp < NJP; jp++) acc[jp] = pb2[jp];
            const ulonglong2* W2q = (const ulonglong2*)sW2;
            #pragma unroll 4
            for (int k = 0; k < 128; k++) {
                float hk = sH[k*TPB + tid];
                float hn = (hk - mu) * rstd * sg1[k] + sbe1[k];
                u64 hh = pk2(hn, hn);
                #pragma unroll
                for (int jq = 0; jq < 32; jq++) {
                    ulonglong2 w = W2q[k*32 + jq];
                    acc[2*jq]   = ffma2(hh, w.x, acc[2*jq]);
                    acc[2*jq+1] = ffma2(hh, w.y, acc[2*jq+1]);
                }
            }
        }
        #pragma unroll
        for (int jp = 0; jp < NJP; jp++) {
            float a0, a1; upk2(acc[jp], a0, a1);
            sH[(2*jp)*TPB + tid]   = a0;
            sH[(2*jp+1)*TPB + tid] = a1;
        }
        sum = 0.f; sq = 0.f;
        #pragma unroll 4
        for (int k = 0; k < 128; k++) {
            float a = gelu_f(sH[k*TPB + tid]);
            sH[k*TPB + tid] = a;
            sum += a; sq += a*a;
        }
        mu   = sum * (1.f/128.f);
        var  = sq  * (1.f/128.f) - mu*mu;
        rstd = rsqrtf(var + 1e-5f);

        // ---- GEMM3: (128)->(7) ----
        float a3[8];
        #pragma unroll
        for (int j = 0; j < 8; j++) a3[j] = sb3[j];
        #pragma unroll 8
        for (int k = 0; k < 128; k++) {
            float hk = sH[k*TPB + tid];
            float hn = (hk - mu) * rstd * sg2[k] + sbe2[k];
            const float4* w4 = (const float4*)(sW3 + k*8);
            float4 wa = w4[0], wb = w4[1];
            a3[0] += hn*wa.x; a3[1] += hn*wa.y; a3[2] += hn*wa.z; a3[3] += hn*wa.w;
            a3[4] += hn*wb.x; a3[5] += hn*wb.y; a3[6] += hn*wb.z;
        }

        float ss = 1.f / (1.f + expf(-slog[it]));
        #pragma unroll
        for (int j = 0; j < 7; j++) {
            float nv = th[j] + ss * a3[j];
            th[j] = fminf(fmaxf(nv, LO[j]), HI[j]);
        }
        fk_eval(th, kp);

        const size_t w = (size_t)(it + 1);
        #pragma unroll
        for (int j = 0; j < 7; j++)  outA[w*(size_t)Bn*7  + (size_t)b*7  + j] = th[j];
        #pragma unroll
        for (int j = 0; j < 21; j++) outK[w*(size_t)Bn*21 + (size_t)b*21 + j] = kp[j];
    }

    // final theta (B,7) then final kp (B,7,3)
    #pragma unroll
    for (int j = 0; j < 7; j++)  out[(size_t)b*7 + j] = th[j];
    #pragma unroll
    for (int j = 0; j < 21; j++) out[(size_t)7*Bn + (size_t)b*21 + j] = kp[j];
}

extern "C" void kernel_launch(void* const* d_in, const int* in_sizes, int n_in,
                              void* d_out, int out_size)
{
    const float* ang  = (const float*)d_in[0];   // initial_angles (B,7)
    const float* tgt  = (const float*)d_in[1];   // target_2d (B,7,2)
    const float* Kc   = (const float*)d_in[2];   // camera_K (B,3,3)
    // d_in[3] = original_size (unused)
    const float* Re   = (const float*)d_in[4];   // R_ext (B,3,3)
    const float* te   = (const float*)d_in[5];   // t_ext (B,3)
    const int*   vmk  = (const int*)d_in[6];     // valid_mask (B,) bool -> int32
    const float* W1   = (const float*)d_in[7];
    const float* b1   = (const float*)d_in[8];
    const float* g1   = (const float*)d_in[9];
    const float* be1  = (const float*)d_in[10];
    const float* W2   = (const float*)d_in[11];
    const float* b2   = (const float*)d_in[12];
    const float* g2   = (const float*)d_in[13];
    const float* be2  = (const float*)d_in[14];
    const float* W3   = (const float*)d_in[15];
    const float* b3   = (const float*)d_in[16];
    const float* slog = (const float*)d_in[17];  // step_logits (3,)

    const int Bn = in_sizes[0] / 7;
    const size_t smem = (size_t)SMEM_FLOATS * sizeof(float);

    cudaFuncSetAttribute(irm_kernel, cudaFuncAttributeMaxDynamicSharedMemorySize, (int)smem);

    const int grid = (Bn + TPB - 1) / TPB;
    irm_kernel<<<grid, TPB, smem>>>(ang, tgt, Kc, Re, te, vmk,
                                    W1, b1, g1, be1, W2, b2, g2, be2, W3, b3,
                                    slog, (float*)d_out, Bn);
}